// round 10
// baseline (speedup 1.0000x reference)
#include <cuda_runtime.h>

#define Ld 4096
#define Hd 512
#define Md 1024
#define G4H 2048
#define NCTA 128

// ---------------- scratch (device globals; no allocations allowed) ------------
__device__ float g_x0[Ld * Hd];          // x after embed; then x+att@A in place
__device__ float g_scores[Ld * Md];      // raw scores
__device__ float g_pmax[32 * Md];        // per-block-row partial max
__device__ float g_psum[32 * Md];        // per-block-row partial sum
__device__ unsigned long long g_hpair[2][Hd];   // {tag(hi32), value bits(lo32)}

// ---------------- helpers ------------------------------------------------------
__device__ __forceinline__ unsigned long long ld_acq_u64(const unsigned long long* p) {
    unsigned long long v;
    asm volatile("ld.acquire.gpu.global.b64 %0, [%1];" : "=l"(v) : "l"(p) : "memory");
    return v;
}
__device__ __forceinline__ void st_rel_u64(unsigned long long* p, unsigned long long v) {
    asm volatile("st.release.gpu.global.b64 [%0], %1;" :: "l"(p), "l"(v) : "memory");
}
__device__ __forceinline__ float sigf(float x) { return 1.0f / (1.0f + __expf(-x)); }
__device__ __forceinline__ float tanh_acc(float x) {
    return fmaf(2.0f, 1.0f / (1.0f + __expf(-2.0f * x)), -1.0f);
}

// ---------------- embedding gather (+ g_hpair init) -----------------------------
__global__ __launch_bounds__(128) void embed_kernel(const int* __restrict__ sent,
                                                    const float* __restrict__ embed) {
    if (blockIdx.x < 8)
        ((unsigned long long*)g_hpair)[blockIdx.x * 128 + threadIdx.x] = 0ull;
    int l = blockIdx.x;
    int idx = sent[l];
    const float4* src = (const float4*)(embed + (size_t)idx * Hd);
    float4* dst = (float4*)(g_x0 + (size_t)l * Hd);
    dst[threadIdx.x] = src[threadIdx.x];
}

// ---------------- SGEMM (NT) + fused per-block-row softmax stats ----------------
// C[M,N] = A[M,K] * B[N,K]^T ; also writes partial (max,sum) over this block's
// 128 rows for each of its 128 columns into g_pmax/g_psum[by][col].
#define BM 128
#define BN 128
#define BK 16
__global__ __launch_bounds__(256) void gemm_nt_stats_kernel(
    float* __restrict__ C, const float* __restrict__ A, const float* __restrict__ B,
    int M, int N, int K)
{
    __shared__ float As[BK][BM + 4];
    __shared__ float Bs[BK][BN + 4];
    __shared__ float pm_s[16][128];
    __shared__ float ps_s[16][128];
    int tid = threadIdx.x;
    int bm = blockIdx.y * BM, bn = blockIdx.x * BN;
    int tx = tid & 15, ty = tid >> 4;
    float acc[8][8] = {};
    for (int kk = 0; kk < K; kk += BK) {
#pragma unroll
        for (int i = 0; i < 2; i++) {
            int idx = tid + i * 256;
            int row = idx >> 2, kc = (idx & 3) << 2;
            float4 v = *(const float4*)(A + (size_t)(bm + row) * K + kk + kc);
            As[kc + 0][row] = v.x; As[kc + 1][row] = v.y;
            As[kc + 2][row] = v.z; As[kc + 3][row] = v.w;
        }
#pragma unroll
        for (int i = 0; i < 2; i++) {
            int idx = tid + i * 256;
            int row = idx >> 2, kc = (idx & 3) << 2;
            float4 v = *(const float4*)(B + (size_t)(bn + row) * K + kk + kc);
            Bs[kc + 0][row] = v.x; Bs[kc + 1][row] = v.y;
            Bs[kc + 2][row] = v.z; Bs[kc + 3][row] = v.w;
        }
        __syncthreads();
#pragma unroll
        for (int k = 0; k < BK; k++) {
            float ar[8], br[8];
            *(float4*)(ar)     = *(const float4*)&As[k][ty * 8];
            *(float4*)(ar + 4) = *(const float4*)&As[k][ty * 8 + 4];
            *(float4*)(br)     = *(const float4*)&Bs[k][tx * 8];
            *(float4*)(br + 4) = *(const float4*)&Bs[k][tx * 8 + 4];
#pragma unroll
            for (int i = 0; i < 8; i++)
#pragma unroll
                for (int j = 0; j < 8; j++)
                    acc[i][j] = fmaf(ar[i], br[j], acc[i][j]);
        }
        __syncthreads();
    }
#pragma unroll
    for (int i = 0; i < 8; i++) {
        float* cp = C + (size_t)(bm + ty * 8 + i) * N + bn + tx * 8;
#pragma unroll
        for (int j = 0; j < 8; j++) cp[j] = acc[i][j];
    }
    // per-thread stats over its 8 rows, per column
#pragma unroll
    for (int j = 0; j < 8; j++) {
        float m = acc[0][j];
#pragma unroll
        for (int i = 1; i < 8; i++) m = fmaxf(m, acc[i][j]);
        float s = 0.f;
#pragma unroll
        for (int i = 0; i < 8; i++) s += __expf(acc[i][j] - m);
        pm_s[ty][tx * 8 + j] = m;
        ps_s[ty][tx * 8 + j] = s;
    }
    __syncthreads();
    if (tid < 128) {
        float mm = -3.4e38f;
#pragma unroll
        for (int k = 0; k < 16; k++) mm = fmaxf(mm, pm_s[k][tid]);
        float ss = 0.f;
#pragma unroll
        for (int k = 0; k < 16; k++) ss += ps_s[k][tid] * __expf(pm_s[k][tid] - mm);
        g_pmax[(size_t)blockIdx.y * Md + bn + tid] = mm;
        g_psum[(size_t)blockIdx.y * Md + bn + tid] = ss;
    }
}

// ---------------- SGEMM (NN) with fused softmax on A -----------------------------
// Combines the 32 partial stats per column at block start (smem), then
// C[M,N] = softmaxA[M,K] * B[K,N] + addend.
__global__ __launch_bounds__(256) void gemm_nn_smax_kernel(
    float* __restrict__ C, const float* __restrict__ A, const float* __restrict__ B,
    int M, int N, int K, const float* __restrict__ addend)
{
    __shared__ float As[BK][BM + 4];
    __shared__ float Bs[BK][BN + 4];
    __shared__ float cm_s[Md];
    __shared__ float cr_s[Md];
    int tid = threadIdx.x;
    int bm = blockIdx.y * BM, bn = blockIdx.x * BN;
    int tx = tid & 15, ty = tid >> 4;
    // combine partial column stats (32 row-blocks)
    for (int c = tid; c < Md; c += 256) {
        float mm = -3.4e38f;
#pragma unroll 8
        for (int b = 0; b < 32; b++) mm = fmaxf(mm, g_pmax[(size_t)b * Md + c]);
        float ss = 0.f;
#pragma unroll 8
        for (int b = 0; b < 32; b++)
            ss += g_psum[(size_t)b * Md + c] * __expf(g_pmax[(size_t)b * Md + c] - mm);
        cm_s[c] = mm;
        cr_s[c] = 1.0f / ss;
    }
    __syncthreads();

    float acc[8][8] = {};
    for (int kk = 0; kk < K; kk += BK) {
#pragma unroll
        for (int i = 0; i < 2; i++) {
            int idx = tid + i * 256;
            int row = idx >> 2, kc = (idx & 3) << 2;
            float4 v = *(const float4*)(A + (size_t)(bm + row) * K + kk + kc);
            As[kc + 0][row] = __expf(v.x - cm_s[kk + kc + 0]) * cr_s[kk + kc + 0];
            As[kc + 1][row] = __expf(v.y - cm_s[kk + kc + 1]) * cr_s[kk + kc + 1];
            As[kc + 2][row] = __expf(v.z - cm_s[kk + kc + 2]) * cr_s[kk + kc + 2];
            As[kc + 3][row] = __expf(v.w - cm_s[kk + kc + 3]) * cr_s[kk + kc + 3];
        }
#pragma unroll
        for (int i = 0; i < 2; i++) {
            int idx = tid + i * 256;
            int kr = idx >> 5, col = (idx & 31) << 2;
            float4 v = *(const float4*)(B + (size_t)(kk + kr) * N + bn + col);
            *(float4*)&Bs[kr][col] = v;
        }
        __syncthreads();
#pragma unroll
        for (int k = 0; k < BK; k++) {
            float ar[8], br[8];
            *(float4*)(ar)     = *(const float4*)&As[k][ty * 8];
            *(float4*)(ar + 4) = *(const float4*)&As[k][ty * 8 + 4];
            *(float4*)(br)     = *(const float4*)&Bs[k][tx * 8];
            *(float4*)(br + 4) = *(const float4*)&Bs[k][tx * 8 + 4];
#pragma unroll
            for (int i = 0; i < 8; i++)
#pragma unroll
                for (int j = 0; j < 8; j++)
                    acc[i][j] = fmaf(ar[i], br[j], acc[i][j]);
        }
        __syncthreads();
    }
#pragma unroll
    for (int i = 0; i < 8; i++) {
        size_t off = (size_t)(bm + ty * 8 + i) * N + bn + tx * 8;
        float* cp = C + off;
        const float* ap = addend + off;
#pragma unroll
        for (int j = 0; j < 8; j++) cp[j] = acc[i][j] + ap[j];
    }
}

// ---------------- A -> A_new[0:1024] copy ---------------------------------------
__global__ __launch_bounds__(256) void copyA_kernel(const float* __restrict__ A,
                                                    float* __restrict__ dst) {
    size_t i = (size_t)blockIdx.x * blockDim.x + threadIdx.x;   // float4 index
    ((float4*)dst)[i] = ((const float4*)A)[i];
}

// ---------------- persistent LSTM scan (pre-GEMM fused in) -----------------------
// 128 CTAs x 256 threads. CTA b owns h indices [4b,4b+4) -> 16 gate rows.
// Warp w: gate rows 2w,2w+1. Lane l: h-slice [16l,16l+16).
// W_ih rows held in smem; x[t+1]·W_ih computed in the publish->poll wait window
// (no h dependency -> fully pipelined, zero critical-path cost).
// Exchange: R4/R9 self-validating tagged u64 words, release/acquire.
__global__ __launch_bounds__(256, 1) void lstm_kernel(
    const float* __restrict__ Whh, const float* __restrict__ Wih,
    const float* __restrict__ b_ih, const float* __restrict__ b_hh,
    const float* __restrict__ h0, const float* __restrict__ c0,
    float* __restrict__ out_h, float* __restrict__ out_c,
    float* __restrict__ out_seq, float* __restrict__ out_anew_last)
{
    __shared__ __align__(16) float wih_s[16][Hd];   // 32 KB
    __shared__ __align__(16) float hs[Hd];
    __shared__ __align__(16) float xrow_s[Hd];
    __shared__ float gs[16];
    int bid = blockIdx.x, tid = threadIdx.x;
    int w = tid >> 5, l = tid & 31;
    int rl0 = 2 * w, rl1 = 2 * w + 1;
    int grow0 = (rl0 >> 2) * Hd + bid * 4 + (rl0 & 3);
    int grow1 = (rl1 >> 2) * Hd + bid * 4 + (rl1 & 3);

    // W_hh fragments in registers (as R9)
    float wr0[16], wr1[16];
    {
        const float4* p0 = (const float4*)(Whh + (size_t)grow0 * Hd + l * 16);
        const float4* p1 = (const float4*)(Whh + (size_t)grow1 * Hd + l * 16);
#pragma unroll
        for (int m = 0; m < 4; m++) {
            float4 v0 = p0[m], v1 = p1[m];
            wr0[4 * m + 0] = v0.x; wr0[4 * m + 1] = v0.y;
            wr0[4 * m + 2] = v0.z; wr0[4 * m + 3] = v0.w;
            wr1[4 * m + 0] = v1.x; wr1[4 * m + 1] = v1.y;
            wr1[4 * m + 2] = v1.z; wr1[4 * m + 3] = v1.w;
        }
    }
    // W_ih rows into smem (16 rows x 512)
    for (int idx = tid; idx < 16 * 128; idx += 256) {
        int rl = idx >> 7, k4 = idx & 127;
        int grow = (rl >> 2) * Hd + bid * 4 + (rl & 3);
        ((float4*)&wih_s[rl][0])[k4] = ((const float4*)(Wih + (size_t)grow * Hd))[k4];
    }
    float bsum0 = b_ih[grow0] + b_hh[grow0];
    float bsum1 = b_ih[grow1] + b_hh[grow1];

    hs[tid] = h0[tid];
    hs[tid + 256] = h0[tid + 256];
    if (tid < 128) ((float4*)xrow_s)[tid] = ((const float4*)g_x0)[tid];  // x[0]
    float creg = (tid < 4) ? c0[bid * 4 + tid] : 0.f;
    __syncthreads();

    // xdot for t=0
    float xd0 = 0.f, xd1 = 0.f;
    {
        float a0 = 0.f, a1 = 0.f;
#pragma unroll
        for (int m = 0; m < 4; m++) {
            float4 xv = *(const float4*)&xrow_s[l * 16 + 4 * m];
            const float* w0 = &wih_s[rl0][l * 16 + 4 * m];
            const float* w1 = &wih_s[rl1][l * 16 + 4 * m];
            a0 = fmaf(w0[0], xv.x, a0); a1 = fmaf(w1[0], xv.x, a1);
            a0 = fmaf(w0[1], xv.y, a0); a1 = fmaf(w1[1], xv.y, a1);
            a0 = fmaf(w0[2], xv.z, a0); a1 = fmaf(w1[2], xv.z, a1);
            a0 = fmaf(w0[3], xv.w, a0); a1 = fmaf(w1[3], xv.w, a1);
        }
#pragma unroll
        for (int off = 16; off > 0; off >>= 1) {
            a0 += __shfl_down_sync(0xffffffffu, a0, off);
            a1 += __shfl_down_sync(0xffffffffu, a1, off);
        }
        xd0 = a0 + bsum0;   // valid in lane 0
        xd1 = a1 + bsum1;
    }

    for (int t = 0; t < Ld; t++) {
        // h-dot over the owned 16-slice
        float a0 = 0.f, a1 = 0.f;
#pragma unroll
        for (int m = 0; m < 4; m++) {
            float4 h4 = *(const float4*)&hs[l * 16 + 4 * m];
            a0 = fmaf(wr0[4 * m + 0], h4.x, a0); a1 = fmaf(wr1[4 * m + 0], h4.x, a1);
            a0 = fmaf(wr0[4 * m + 1], h4.y, a0); a1 = fmaf(wr1[4 * m + 1], h4.y, a1);
            a0 = fmaf(wr0[4 * m + 2], h4.z, a0); a1 = fmaf(wr1[4 * m + 2], h4.z, a1);
            a0 = fmaf(wr0[4 * m + 3], h4.w, a0); a1 = fmaf(wr1[4 * m + 3], h4.w, a1);
        }
#pragma unroll
        for (int off = 16; off > 0; off >>= 1) {
            a0 += __shfl_down_sync(0xffffffffu, a0, off);
            a1 += __shfl_down_sync(0xffffffffu, a1, off);
        }
        if (l == 0) { gs[rl0] = a0 + xd0; gs[rl1] = a1 + xd1; }
        __syncthreads();

        int nb = (t + 1) & 1;
        unsigned tgt = (unsigned)(t + 1);

        if (tid < 4) {
            float iv = sigf(gs[tid]);
            float fv = sigf(gs[4 + tid]);
            float gv = tanh_acc(gs[8 + tid]);
            float ov = sigf(gs[12 + tid]);
            float cv = fmaf(fv, creg, iv * gv);
            creg = cv;
            float hv = ov * tanh_acc(cv);
            int hidx = bid * 4 + tid;
            unsigned long long pkt =
                ((unsigned long long)tgt << 32) | (unsigned long long)__float_as_uint(hv);
            st_rel_u64(&g_hpair[nb][hidx], pkt);          // strong release publish
            __stcg(&out_seq[(size_t)t * Hd + hidx], hv);
            if (t == Ld - 1) {
                out_h[hidx] = hv;
                out_c[hidx] = cv;
                out_anew_last[hidx] = hv;
            }
        }
        if (t == Ld - 1) break;

        // ---- wait-window work: x[t+1] row load + xdot for t+1 ----
        if (tid < 128)
            ((float4*)xrow_s)[tid] =
                __ldcg(((const float4*)(g_x0 + (size_t)(t + 1) * Hd)) + tid);
        __syncthreads();
        {
            float b0 = 0.f, b1 = 0.f;
#pragma unroll
            for (int m = 0; m < 4; m++) {
                float4 xv = *(const float4*)&xrow_s[l * 16 + 4 * m];
                const float* w0 = &wih_s[rl0][l * 16 + 4 * m];
                const float* w1 = &wih_s[rl1][l * 16 + 4 * m];
                b0 = fmaf(w0[0], xv.x, b0); b1 = fmaf(w1[0], xv.x, b1);
                b0 = fmaf(w0[1], xv.y, b0); b1 = fmaf(w1[1], xv.y, b1);
                b0 = fmaf(w0[2], xv.z, b0); b1 = fmaf(w1[2], xv.z, b1);
                b0 = fmaf(w0[3], xv.w, b0); b1 = fmaf(w1[3], xv.w, b1);
            }
#pragma unroll
            for (int off = 16; off > 0; off >>= 1) {
                b0 += __shfl_down_sync(0xffffffffu, b0, off);
                b1 += __shfl_down_sync(0xffffffffu, b1, off);
            }
            xd0 = b0 + bsum0;
            xd1 = b1 + bsum1;
        }

        // poll BOTH tagged words concurrently (R9)
        {
            const unsigned long long* p0 = &g_hpair[nb][tid];
            const unsigned long long* p1 = &g_hpair[nb][tid + 256];
            unsigned long long v0 = ld_acq_u64(p0);
            unsigned long long v1 = ld_acq_u64(p1);
            bool ok0 = (unsigned)(v0 >> 32) >= tgt;
            bool ok1 = (unsigned)(v1 >> 32) >= tgt;
            while (!(ok0 && ok1)) {
                if (!ok0) { v0 = ld_acq_u64(p0); ok0 = (unsigned)(v0 >> 32) >= tgt; }
                if (!ok1) { v1 = ld_acq_u64(p1); ok1 = (unsigned)(v1 >> 32) >= tgt; }
            }
            hs[tid]       = __uint_as_float((unsigned)v0);
            hs[tid + 256] = __uint_as_float((unsigned)v1);
        }
        __syncthreads();
    }
}

// ---------------- launch ---------------------------------------------------------
extern "C" void kernel_launch(void* const* d_in, const int* in_sizes, int n_in,
                              void* d_out, int out_size) {
    const int*   sent  = (const int*)d_in[0];
    const float* h0    = (const float*)d_in[1];
    const float* c0    = (const float*)d_in[2];
    const float* A     = (const float*)d_in[3];
    const float* embed = (const float*)d_in[4];
    const float* W_ih  = (const float*)d_in[5];
    const float* W_hh  = (const float*)d_in[6];
    const float* b_ih  = (const float*)d_in[7];
    const float* b_hh  = (const float*)d_in[8];

    float* out = (float*)d_out;
    float* out_h = out;
    float* out_c = out + Hd;
    float* out_seq = out + 2 * Hd;
    float* out_anew = out + 2 * Hd + (size_t)Ld * Hd;
    float* out_anew_last = out_anew + (size_t)Md * Hd;

    float* d_x0; float* d_scores;
    cudaGetSymbolAddress((void**)&d_x0, g_x0);
    cudaGetSymbolAddress((void**)&d_scores, g_scores);

    // launch 0: embed (+ g_hpair init)
    embed_kernel<<<Ld, 128>>>(sent, embed);
    // launch 1: scores = x0 @ A^T + fused per-block-row softmax stats
    gemm_nt_stats_kernel<<<dim3(Md / BN, Ld / BM), 256>>>(d_scores, d_x0, A,
                                                          Ld, Md, Hd);
    // launch 2: x = x0 + softmax(scores) @ A (stats combined in-kernel)
    gemm_nn_smax_kernel<<<dim3(Hd / BN, Ld / BM), 256>>>(d_x0, d_scores, A,
                                                         Ld, Hd, Md, d_x0);
    // launch 3: LSTM scan (pre-GEMM fused; persistent 128 CTAs) — profiled slot
    lstm_kernel<<<NCTA, 256>>>(W_hh, W_ih, b_ih, b_hh, h0, c0,
                               out_h, out_c, out_seq, out_anew_last);
    // launch 4: A_new rows 0..1023 (independent; after scan)
    copyA_kernel<<<(Md * Hd / 4) / 256, 256>>>(A, out_anew);
}

// round 11
// speedup vs baseline: 1.2440x; 1.2440x over previous
#include <cuda_runtime.h>

#define Ld 4096
#define Hd 512
#define Md 1024
#define G4H 2048
#define NCTA 128

// ---------------- scratch (device globals; no allocations allowed) ------------
__device__ float g_x0[Ld * Hd];          // x = embed + att@A
__device__ float g_scores[Ld * Md];      // raw scores
__device__ float g_pre[Ld * G4H];        // x @ W_ih^T + b_ih + b_hh
__device__ float g_pmax[32 * Md];        // per-block-row partial max
__device__ float g_psum[32 * Md];        // per-block-row partial sum
__device__ unsigned long long g_hpair[2][Hd];   // {tag(hi32), value bits(lo32)}

// ---------------- helpers ------------------------------------------------------
__device__ __forceinline__ unsigned long long ld_acq_u64(const unsigned long long* p) {
    unsigned long long v;
    asm volatile("ld.acquire.gpu.global.b64 %0, [%1];" : "=l"(v) : "l"(p) : "memory");
    return v;
}
__device__ __forceinline__ void st_rel_u64(unsigned long long* p, unsigned long long v) {
    asm volatile("st.release.gpu.global.b64 [%0], %1;" :: "l"(p), "l"(v) : "memory");
}
__device__ __forceinline__ float sigf(float x) { return 1.0f / (1.0f + __expf(-x)); }
__device__ __forceinline__ float tanh_acc(float x) {
    return fmaf(2.0f, 1.0f / (1.0f + __expf(-2.0f * x)), -1.0f);
}

#define BM 128
#define BN 128
#define BK 16

// ---------------- SGEMM (NT) + embed gather + per-block-row softmax stats -------
// scores[l,m] = embed[sent[l]] . A[m]   (A-tiles gathered via sent)
// Also: partial (max,sum) over this block's 128 rows per column, and g_hpair init.
__global__ __launch_bounds__(256) void gemm_nt_stats_embed_kernel(
    float* __restrict__ C, const int* __restrict__ sent,
    const float* __restrict__ embed, const float* __restrict__ B,
    int M, int N, int K)
{
    __shared__ float As[BK][BM + 4];
    __shared__ float Bs[BK][BN + 4];
    __shared__ int sent_s[BM];
    __shared__ float pm_s[16][128];
    __shared__ float ps_s[16][128];
    int tid = threadIdx.x;
    int bm = blockIdx.y * BM, bn = blockIdx.x * BN;
    int tx = tid & 15, ty = tid >> 4;

    // fold in g_hpair init (1024 u64 words; 4 blocks cover it)
    if (blockIdx.x == 0 && blockIdx.y < 4)
        ((unsigned long long*)g_hpair)[blockIdx.y * 256 + tid] = 0ull;
    if (tid < BM) sent_s[tid] = sent[bm + tid];
    __syncthreads();

    float acc[8][8] = {};
    for (int kk = 0; kk < K; kk += BK) {
#pragma unroll
        for (int i = 0; i < 2; i++) {
            int idx = tid + i * 256;
            int row = idx >> 2, kc = (idx & 3) << 2;
            float4 v = *(const float4*)(embed + (size_t)sent_s[row] * K + kk + kc);
            As[kc + 0][row] = v.x; As[kc + 1][row] = v.y;
            As[kc + 2][row] = v.z; As[kc + 3][row] = v.w;
        }
#pragma unroll
        for (int i = 0; i < 2; i++) {
            int idx = tid + i * 256;
            int row = idx >> 2, kc = (idx & 3) << 2;
            float4 v = *(const float4*)(B + (size_t)(bn + row) * K + kk + kc);
            Bs[kc + 0][row] = v.x; Bs[kc + 1][row] = v.y;
            Bs[kc + 2][row] = v.z; Bs[kc + 3][row] = v.w;
        }
        __syncthreads();
#pragma unroll
        for (int k = 0; k < BK; k++) {
            float ar[8], br[8];
            *(float4*)(ar)     = *(const float4*)&As[k][ty * 8];
            *(float4*)(ar + 4) = *(const float4*)&As[k][ty * 8 + 4];
            *(float4*)(br)     = *(const float4*)&Bs[k][tx * 8];
            *(float4*)(br + 4) = *(const float4*)&Bs[k][tx * 8 + 4];
#pragma unroll
            for (int i = 0; i < 8; i++)
#pragma unroll
                for (int j = 0; j < 8; j++)
                    acc[i][j] = fmaf(ar[i], br[j], acc[i][j]);
        }
        __syncthreads();
    }
#pragma unroll
    for (int i = 0; i < 8; i++) {
        float* cp = C + (size_t)(bm + ty * 8 + i) * N + bn + tx * 8;
#pragma unroll
        for (int j = 0; j < 8; j++) cp[j] = acc[i][j];
    }
    // per-thread stats over its 8 rows, per column
#pragma unroll
    for (int j = 0; j < 8; j++) {
        float m = acc[0][j];
#pragma unroll
        for (int i = 1; i < 8; i++) m = fmaxf(m, acc[i][j]);
        float s = 0.f;
#pragma unroll
        for (int i = 0; i < 8; i++) s += __expf(acc[i][j] - m);
        pm_s[ty][tx * 8 + j] = m;
        ps_s[ty][tx * 8 + j] = s;
    }
    __syncthreads();
    if (tid < 128) {
        float mm = -3.4e38f;
#pragma unroll
        for (int k = 0; k < 16; k++) mm = fmaxf(mm, pm_s[k][tid]);
        float ss = 0.f;
#pragma unroll
        for (int k = 0; k < 16; k++) ss += ps_s[k][tid] * __expf(pm_s[k][tid] - mm);
        g_pmax[(size_t)blockIdx.y * Md + bn + tid] = mm;
        g_psum[(size_t)blockIdx.y * Md + bn + tid] = ss;
    }
}

// ---------------- SGEMM (NN) + fused softmax on A + embed addend -----------------
// x[l,n] = embed[sent[l],n] + sum_k softmax(scores)[l,k] * A[k,n]
__global__ __launch_bounds__(256) void gemm_nn_smax_embed_kernel(
    float* __restrict__ C, const float* __restrict__ A, const float* __restrict__ B,
    const int* __restrict__ sent, const float* __restrict__ embed,
    int M, int N, int K)
{
    __shared__ float As[BK][BM + 4];
    __shared__ float Bs[BK][BN + 4];
    __shared__ float cm_s[Md];
    __shared__ float cr_s[Md];
    __shared__ int sent_s[BM];
    int tid = threadIdx.x;
    int bm = blockIdx.y * BM, bn = blockIdx.x * BN;
    int tx = tid & 15, ty = tid >> 4;
    if (tid < BM) sent_s[tid] = sent[bm + tid];
    // combine partial column stats (32 row-blocks)
    for (int c = tid; c < Md; c += 256) {
        float mm = -3.4e38f;
#pragma unroll 8
        for (int b = 0; b < 32; b++) mm = fmaxf(mm, g_pmax[(size_t)b * Md + c]);
        float ss = 0.f;
#pragma unroll 8
        for (int b = 0; b < 32; b++)
            ss += g_psum[(size_t)b * Md + c] * __expf(g_pmax[(size_t)b * Md + c] - mm);
        cm_s[c] = mm;
        cr_s[c] = 1.0f / ss;
    }
    __syncthreads();

    float acc[8][8] = {};
    for (int kk = 0; kk < K; kk += BK) {
#pragma unroll
        for (int i = 0; i < 2; i++) {
            int idx = tid + i * 256;
            int row = idx >> 2, kc = (idx & 3) << 2;
            float4 v = *(const float4*)(A + (size_t)(bm + row) * K + kk + kc);
            As[kc + 0][row] = __expf(v.x - cm_s[kk + kc + 0]) * cr_s[kk + kc + 0];
            As[kc + 1][row] = __expf(v.y - cm_s[kk + kc + 1]) * cr_s[kk + kc + 1];
            As[kc + 2][row] = __expf(v.z - cm_s[kk + kc + 2]) * cr_s[kk + kc + 2];
            As[kc + 3][row] = __expf(v.w - cm_s[kk + kc + 3]) * cr_s[kk + kc + 3];
        }
#pragma unroll
        for (int i = 0; i < 2; i++) {
            int idx = tid + i * 256;
            int kr = idx >> 5, col = (idx & 31) << 2;
            float4 v = *(const float4*)(B + (size_t)(kk + kr) * N + bn + col);
            *(float4*)&Bs[kr][col] = v;
        }
        __syncthreads();
#pragma unroll
        for (int k = 0; k < BK; k++) {
            float ar[8], br[8];
            *(float4*)(ar)     = *(const float4*)&As[k][ty * 8];
            *(float4*)(ar + 4) = *(const float4*)&As[k][ty * 8 + 4];
            *(float4*)(br)     = *(const float4*)&Bs[k][tx * 8];
            *(float4*)(br + 4) = *(const float4*)&Bs[k][tx * 8 + 4];
#pragma unroll
            for (int i = 0; i < 8; i++)
#pragma unroll
                for (int j = 0; j < 8; j++)
                    acc[i][j] = fmaf(ar[i], br[j], acc[i][j]);
        }
        __syncthreads();
    }
#pragma unroll
    for (int i = 0; i < 8; i++) {
        float* cp = C + (size_t)(bm + ty * 8 + i) * N + bn + tx * 8;
        const float* ep = embed + (size_t)sent_s[ty * 8 + i] * N + bn + tx * 8;
#pragma unroll
        for (int j = 0; j < 8; j++) cp[j] = acc[i][j] + ep[j];
    }
}

// ---------------- tiled SGEMM (NT) with biases: pre = x @ W_ih^T + b1 + b2 ------
__global__ __launch_bounds__(256) void gemm_nt_bias_kernel(
    float* __restrict__ C, const float* __restrict__ A, const float* __restrict__ B,
    int M, int N, int K, const float* __restrict__ bias1, const float* __restrict__ bias2)
{
    __shared__ float As[BK][BM + 4];
    __shared__ float Bs[BK][BN + 4];
    int tid = threadIdx.x;
    int bm = blockIdx.y * BM, bn = blockIdx.x * BN;
    int tx = tid & 15, ty = tid >> 4;
    float acc[8][8] = {};
    for (int kk = 0; kk < K; kk += BK) {
#pragma unroll
        for (int i = 0; i < 2; i++) {
            int idx = tid + i * 256;
            int row = idx >> 2, kc = (idx & 3) << 2;
            float4 v = *(const float4*)(A + (size_t)(bm + row) * K + kk + kc);
            As[kc + 0][row] = v.x; As[kc + 1][row] = v.y;
            As[kc + 2][row] = v.z; As[kc + 3][row] = v.w;
        }
#pragma unroll
        for (int i = 0; i < 2; i++) {
            int idx = tid + i * 256;
            int row = idx >> 2, kc = (idx & 3) << 2;
            float4 v = *(const float4*)(B + (size_t)(bn + row) * K + kk + kc);
            Bs[kc + 0][row] = v.x; Bs[kc + 1][row] = v.y;
            Bs[kc + 2][row] = v.z; Bs[kc + 3][row] = v.w;
        }
        __syncthreads();
#pragma unroll
        for (int k = 0; k < BK; k++) {
            float ar[8], br[8];
            *(float4*)(ar)     = *(const float4*)&As[k][ty * 8];
            *(float4*)(ar + 4) = *(const float4*)&As[k][ty * 8 + 4];
            *(float4*)(br)     = *(const float4*)&Bs[k][tx * 8];
            *(float4*)(br + 4) = *(const float4*)&Bs[k][tx * 8 + 4];
#pragma unroll
            for (int i = 0; i < 8; i++)
#pragma unroll
                for (int j = 0; j < 8; j++)
                    acc[i][j] = fmaf(ar[i], br[j], acc[i][j]);
        }
        __syncthreads();
    }
    float bb[8];
#pragma unroll
    for (int j = 0; j < 8; j++)
        bb[j] = bias1[bn + tx * 8 + j] + bias2[bn + tx * 8 + j];
#pragma unroll
    for (int i = 0; i < 8; i++) {
        float* cp = C + (size_t)(bm + ty * 8 + i) * N + bn + tx * 8;
#pragma unroll
        for (int j = 0; j < 8; j++) cp[j] = acc[i][j] + bb[j];
    }
}

// ---------------- A -> A_new[0:1024] copy ---------------------------------------
__global__ __launch_bounds__(256) void copyA_kernel(const float* __restrict__ A,
                                                    float* __restrict__ dst) {
    size_t i = (size_t)blockIdx.x * blockDim.x + threadIdx.x;   // float4 index
    ((float4*)dst)[i] = ((const float4*)A)[i];
}

// ---------------- persistent LSTM scan (R9 champion + dedicated publisher warp) --
// 128 CTAs x 256 threads. CTA b owns h[4b,4b+4) -> 16 gate rows.
// Warp w computes gate rows 2w,2w+1; lane l owns h-slice [16l,16l+16).
// Exchange: tagged u64 words, release/acquire (R4/R9 champion protocol).
// NEW: warp 0 (publisher warp) polls NOTHING; warps 1-7 (224 threads) cover all
// 512 words (2-3 each, polled concurrently) -> publish and detect overlap.
__global__ __launch_bounds__(256, 1) void lstm_kernel(
    const float* __restrict__ Whh, const float* __restrict__ h0,
    const float* __restrict__ c0, float* __restrict__ out_h,
    float* __restrict__ out_c, float* __restrict__ out_seq,
    float* __restrict__ out_anew_last)
{
    __shared__ float hs[Hd];
    __shared__ float gs[16];
    int bid = blockIdx.x, tid = threadIdx.x;
    int w = tid >> 5, l = tid & 31;
    int rl0 = 2 * w, rl1 = 2 * w + 1;
    int grow0 = (rl0 >> 2) * Hd + bid * 4 + (rl0 & 3);
    int grow1 = (rl1 >> 2) * Hd + bid * 4 + (rl1 & 3);

    float wr0[16], wr1[16];
    {
        const float4* p0 = (const float4*)(Whh + (size_t)grow0 * Hd + l * 16);
        const float4* p1 = (const float4*)(Whh + (size_t)grow1 * Hd + l * 16);
#pragma unroll
        for (int m = 0; m < 4; m++) {
            float4 v0 = p0[m], v1 = p1[m];
            wr0[4 * m + 0] = v0.x; wr0[4 * m + 1] = v0.y;
            wr0[4 * m + 2] = v0.z; wr0[4 * m + 3] = v0.w;
            wr1[4 * m + 0] = v1.x; wr1[4 * m + 1] = v1.y;
            wr1[4 * m + 2] = v1.z; wr1[4 * m + 3] = v1.w;
        }
    }
    hs[tid] = h0[tid];
    hs[tid + 256] = h0[tid + 256];
    float creg = (tid < 4) ? c0[bid * 4 + tid] : 0.f;
    int pidx = tid - 32;                 // poller index 0..223 (warps 1-7)
    __syncthreads();

    for (int t = 0; t < Ld; t++) {
        // lane0 of each warp prefetches the two pre-activations (overlaps h-dot)
        float2 pre2 = make_float2(0.f, 0.f);
        if (l == 0)
            pre2 = __ldcg((const float2*)&g_pre[(size_t)t * G4H + grow0]);

        // dot products over the owned 16-slice (LDS.128, conflict-free)
        float a0 = 0.f, a1 = 0.f;
#pragma unroll
        for (int m = 0; m < 4; m++) {
            float4 h4 = *(const float4*)&hs[l * 16 + 4 * m];
            a0 = fmaf(wr0[4 * m + 0], h4.x, a0); a1 = fmaf(wr1[4 * m + 0], h4.x, a1);
            a0 = fmaf(wr0[4 * m + 1], h4.y, a0); a1 = fmaf(wr1[4 * m + 1], h4.y, a1);
            a0 = fmaf(wr0[4 * m + 2], h4.z, a0); a1 = fmaf(wr1[4 * m + 2], h4.z, a1);
            a0 = fmaf(wr0[4 * m + 3], h4.w, a0); a1 = fmaf(wr1[4 * m + 3], h4.w, a1);
        }
#pragma unroll
        for (int off = 16; off > 0; off >>= 1) {
            a0 += __shfl_down_sync(0xffffffffu, a0, off);
            a1 += __shfl_down_sync(0xffffffffu, a1, off);
        }
        if (l == 0) { gs[rl0] = a0 + pre2.x; gs[rl1] = a1 + pre2.y; }
        __syncthreads();

        int nb = (t + 1) & 1;
        unsigned tgt = (unsigned)(t + 1);

        if (tid < 4) {
            float iv = sigf(gs[tid]);
            float fv = sigf(gs[4 + tid]);
            float gv = tanh_acc(gs[8 + tid]);
            float ov = sigf(gs[12 + tid]);
            float cv = fmaf(fv, creg, iv * gv);
            creg = cv;
            float hv = ov * tanh_acc(cv);
            int hidx = bid * 4 + tid;
            unsigned long long pkt =
                ((unsigned long long)tgt << 32) | (unsigned long long)__float_as_uint(hv);
            st_rel_u64(&g_hpair[nb][hidx], pkt);          // strong release publish
            __stcg(&out_seq[(size_t)t * Hd + hidx], hv);
            if (t == Ld - 1) {
                out_h[hidx] = hv;
                out_c[hidx] = cv;
                out_anew_last[hidx] = hv;
            }
        }
        if (t == Ld - 1) break;

        // warps 1-7 poll; warp 0 (publisher) goes straight to the barrier
        if (tid >= 32) {
            const unsigned long long* p0 = &g_hpair[nb][pidx];
            const unsigned long long* p1 = &g_hpair[nb][pidx + 224];
            bool three = pidx < 64;
            const unsigned long long* p2 = &g_hpair[nb][pidx + 448];
            unsigned long long v0 = ld_acq_u64(p0);
            unsigned long long v1 = ld_acq_u64(p1);
            unsigned long long v2 = three ? ld_acq_u64(p2) : 0ull;
            bool ok0 = (unsigned)(v0 >> 32) >= tgt;
            bool ok1 = (unsigned)(v1 >> 32) >= tgt;
            bool ok2 = !three || (unsigned)(v2 >> 32) >= tgt;
            while (!(ok0 && ok1 && ok2)) {
                if (!ok0) { v0 = ld_acq_u64(p0); ok0 = (unsigned)(v0 >> 32) >= tgt; }
                if (!ok1) { v1 = ld_acq_u64(p1); ok1 = (unsigned)(v1 >> 32) >= tgt; }
                if (!ok2) { v2 = ld_acq_u64(p2); ok2 = (unsigned)(v2 >> 32) >= tgt; }
            }
            hs[pidx]       = __uint_as_float((unsigned)v0);
            hs[pidx + 224] = __uint_as_float((unsigned)v1);
            if (three) hs[pidx + 448] = __uint_as_float((unsigned)v2);
        }
        __syncthreads();
    }
}

// ---------------- launch ---------------------------------------------------------
extern "C" void kernel_launch(void* const* d_in, const int* in_sizes, int n_in,
                              void* d_out, int out_size) {
    const int*   sent  = (const int*)d_in[0];
    const float* h0    = (const float*)d_in[1];
    const float* c0    = (const float*)d_in[2];
    const float* A     = (const float*)d_in[3];
    const float* embed = (const float*)d_in[4];
    const float* W_ih  = (const float*)d_in[5];
    const float* W_hh  = (const float*)d_in[6];
    const float* b_ih  = (const float*)d_in[7];
    const float* b_hh  = (const float*)d_in[8];

    float* out = (float*)d_out;
    float* out_h = out;
    float* out_c = out + Hd;
    float* out_seq = out + 2 * Hd;
    float* out_anew = out + 2 * Hd + (size_t)Ld * Hd;
    float* out_anew_last = out_anew + (size_t)Md * Hd;

    float* d_x0; float* d_scores; float* d_pre;
    cudaGetSymbolAddress((void**)&d_x0, g_x0);
    cudaGetSymbolAddress((void**)&d_scores, g_scores);
    cudaGetSymbolAddress((void**)&d_pre, g_pre);

    // launch 0: scores = embed[sent] @ A^T (+ stats, + g_hpair init)
    gemm_nt_stats_embed_kernel<<<dim3(Md / BN, Ld / BM), 256>>>(
        d_scores, sent, embed, A, Ld, Md, Hd);
    // launch 1: x = embed[sent] + softmax(scores) @ A
    gemm_nn_smax_embed_kernel<<<dim3(Hd / BN, Ld / BM), 256>>>(
        d_x0, d_scores, A, sent, embed, Ld, Hd, Md);
    // launch 2: pre = x @ W_ih^T + b_ih + b_hh
    gemm_nt_bias_kernel<<<dim3(G4H / BN, Ld / BM), 256>>>(
        d_pre, d_x0, W_ih, Ld, G4H, Hd, b_ih, b_hh);
    // launch 3: LSTM scan (profiled slot)
    lstm_kernel<<<NCTA, 256>>>(W_hh, h0, c0, out_h, out_c, out_seq, out_anew_last);
    // launch 4: A_new rows 0..1023
    copyA_kernel<<<(Md * Hd / 4) / 256, 256>>>(A, out_anew);
}